// round 15
// baseline (speedup 1.0000x reference)
#include <cuda_runtime.h>
#include <cuda_bf16.h>
#include <mma.h>
#include <cstdint>
#include <math.h>

using namespace nvcuda;
typedef __nv_bfloat16 bf16;

// Problem constants (fixed shapes)
#define TOK   131072      // B*H*W = 8*128*128
#define CDIM  192
#define HID   768
#define QKVN  576
#define NHEAD 6
#define SS    4
#define NWIN  2048        // B * 16 * 16

// GEMM tiling: block 128x96, 4 warps (2m x 2n), warp tile 64x48  (proven)
#define BM 128
#define BN 96
#define BK 32
#define LDA 40            // bf16 ld, 80B rows
#define LDB 104           // bf16 ld for B (96+8)
#define LDC 100           // fp32 ld for C half-tile
#define A_STAGE_B (BM * LDA * 2)      // 10240 B
#define B_STAGE_B (BK * LDB * 2)      // 6656 B
#define STAGE_B   (A_STAGE_B + B_STAGE_B)
#define SMEM_BYTES (2 * STAGE_B)      // 33792; C half-tile 64*100*4=25600 fits

// ---------------- scratch (device globals; no allocations allowed) ----------
__device__ bf16  g_qkv[TOK * QKVN];        // window-ordered, bf16
__device__ bf16  g_attnout[TOK * CDIM];    // window-ordered, bf16
__device__ float g_x1[TOK * CDIM];         // fp32 residual spine
__device__ bf16  g_x1n[TOK * CDIM];
__device__ bf16  g_h[TOK * HID];
__device__ bf16  g_wqkv[CDIM * QKVN];
__device__ bf16  g_wproj[CDIM * CDIM];
__device__ bf16  g_w1[CDIM * HID];
__device__ bf16  g_w2[HID * CDIM];

// ---------------- helpers ----------------------------------------------------
__device__ __forceinline__ uint32_t smem_u32(const void* p) {
    uint32_t a;
    asm("{ .reg .u64 t; cvta.to.shared.u64 t, %1; cvt.u32.u64 %0, t; }" : "=r"(a) : "l"(p));
    return a;
}
#define CP_ASYNC16(dst, src) \
    asm volatile("cp.async.cg.shared.global [%0], [%1], 16;" :: "r"(dst), "l"(src))
#define CP_COMMIT() asm volatile("cp.async.commit_group;" ::: "memory")
#define CP_WAIT(n)  asm volatile("cp.async.wait_group %0;" :: "n"(n) : "memory")

#define LDMATRIX_X4(r0, r1, r2, r3, addr) \
    asm volatile("ldmatrix.sync.aligned.m8n8.x4.shared.b16 {%0,%1,%2,%3}, [%4];" \
                 : "=r"(r0), "=r"(r1), "=r"(r2), "=r"(r3) : "r"(addr))
#define LDMATRIX_X4_T(r0, r1, r2, r3, addr) \
    asm volatile("ldmatrix.sync.aligned.m8n8.x4.trans.shared.b16 {%0,%1,%2,%3}, [%4];" \
                 : "=r"(r0), "=r"(r1), "=r"(r2), "=r"(r3) : "r"(addr))

#define MMA_16816(d, a, b0v, b1v) \
    asm volatile("mma.sync.aligned.m16n8k16.row.col.f32.bf16.bf16.f32 " \
                 "{%0,%1,%2,%3}, {%4,%5,%6,%7}, {%8,%9}, {%0,%1,%2,%3};" \
                 : "+f"((d)[0]), "+f"((d)[1]), "+f"((d)[2]), "+f"((d)[3]) \
                 : "r"((a)[0]), "r"((a)[1]), "r"((a)[2]), "r"((a)[3]), \
                   "r"(b0v), "r"(b1v))

__device__ __forceinline__ int map_win_to_global(int r) {
    int w = r >> 6, n = r & 63;
    int b = w >> 8, rem = w & 255;
    int wh = rem >> 4, ww = rem & 15;
    int i = n >> 3, j = n & 7;
    int h  = (wh * 8 + i + SS) & 127;
    int wc = (ww * 8 + j + SS) & 127;
    return (b << 14) + (h << 7) + wc;
}
__device__ __forceinline__ float gelu_exact(float v) {
    return 0.5f * v * (1.0f + erff(v * 0.70710678118654752440f));
}
__device__ __forceinline__ uint32_t pack_bf2(float a, float b) {
    __nv_bfloat162 h = __floats2bfloat162_rn(a, b);
    return *(uint32_t*)&h;
}

// ---------------- fp32 -> bf16 weight conversion ------------------------------
#define S0 (CDIM*QKVN)
#define S1 (CDIM*CDIM)
#define S2 (CDIM*HID)
#define S3 (HID*CDIM)
__global__ void __launch_bounds__(256) conv_w_all(
    const float* __restrict__ w0, const float* __restrict__ w1,
    const float* __restrict__ w2, const float* __restrict__ w3)
{
    const int off = (blockIdx.x * 256 + threadIdx.x) * 8;
    const float* src; bf16* dst; int lo;
    if      (off < S0)            { src = w0; dst = g_wqkv;  lo = off; }
    else if (off < S0+S1)         { src = w1; dst = g_wproj; lo = off - S0; }
    else if (off < S0+S1+S2)      { src = w2; dst = g_w1;    lo = off - S0 - S1; }
    else if (off < S0+S1+S2+S3)   { src = w3; dst = g_w2;    lo = off - S0 - S1 - S2; }
    else return;
    float4 v0 = *(const float4*)(src + lo);
    float4 v1 = *(const float4*)(src + lo + 4);
    uint4 o;
    o.x = pack_bf2(v0.x, v0.y); o.y = pack_bf2(v0.z, v0.w);
    o.z = pack_bf2(v1.x, v1.y); o.w = pack_bf2(v1.z, v1.w);
    *(uint4*)(dst + lo) = o;
}

// ---------------- WMMA bf16 GEMM: 128x96 block, two-sync mainloop -------------
// MODE: 0=QKV(gather A rows from fp32 x, fused cvt; out bf16 g_qkv)
//       1=PROJ(scatter+resid -> fp32 g_x1)
//       2=FC1(gelu -> bf16 g_h)
//       3=FC2(+resid g_x1 -> fp32 Cout)
template<int KDIM, int NDIM, int MODE>
__global__ void __launch_bounds__(128) gemm_bf(
    const float* __restrict__ Ax32,    // MODE0: fp32 x
    const float* __restrict__ bias,
    const float* __restrict__ resid,
    float* __restrict__ Cout)
{
    __shared__ __align__(16) unsigned char smem[SMEM_BYTES];
    bf16* sA[2] = { (bf16*)smem, (bf16*)(smem + STAGE_B) };
    bf16* sB[2] = { (bf16*)(smem + A_STAGE_B), (bf16*)(smem + STAGE_B + A_STAGE_B) };
    float* sC = (float*)smem;

    const int tid = threadIdx.x;
    const int bm = blockIdx.y * BM;
    const int bn = blockIdx.x * BN;

    const bf16* Aptr;
    const bf16* Bptr;
    if      constexpr (MODE == 0) { Aptr = nullptr;   Bptr = g_wqkv; }
    else if constexpr (MODE == 1) { Aptr = g_attnout; Bptr = g_wproj; }
    else if constexpr (MODE == 2) { Aptr = g_x1n;     Bptr = g_w1; }
    else                          { Aptr = g_h;       Bptr = g_w2; }

    int grA;
    if constexpr (MODE == 0) grA = map_win_to_global(bm + tid);
    else                     grA = bm + tid;

    const float* srcA32 = nullptr;
    const bf16*  srcA   = nullptr;
    if constexpr (MODE == 0) srcA32 = Ax32 + (size_t)grA * KDIM;
    else                     srcA   = Aptr + (size_t)grA * KDIM;
    const uint32_t dA0 = smem_u32(sA[0]) + (uint32_t)(tid * LDA * 2);
    const uint32_t dA1 = smem_u32(sA[1]) + (uint32_t)(tid * LDA * 2);

    int bRow[3], bCol[3];
    const bf16* srcB[3];
    uint32_t dBoff[3];
    #pragma unroll
    for (int l = 0; l < 3; l++) {
        int idx = tid + l * 128;
        bRow[l] = idx / 12; bCol[l] = (idx % 12) * 8;
        srcB[l] = Bptr + (size_t)bRow[l] * NDIM + bn + bCol[l];
        dBoff[l] = (uint32_t)((bRow[l] * LDB + bCol[l]) * 2);
    }
    const uint32_t dBb[2] = { smem_u32(sB[0]), smem_u32(sB[1]) };

    constexpr int T = KDIM / BK;
    const int wid = tid >> 5;
    const int wm = wid & 1, wn = wid >> 1;

    wmma::fragment<wmma::accumulator, 16, 16, 16, float> cf[4][3];
    #pragma unroll
    for (int i = 0; i < 4; i++)
        #pragma unroll
        for (int j = 0; j < 3; j++) wmma::fill_fragment(cf[i][j], 0.0f);

    // prologue: stage 0
    if constexpr (MODE == 0) {
        float4 a4[8];
        #pragma unroll
        for (int c = 0; c < 8; c++) a4[c] = *(const float4*)(srcA32 + c * 4);
        #pragma unroll
        for (int c = 0; c < 4; c++) {
            uint4 o;
            o.x = pack_bf2(a4[2*c].x, a4[2*c].y);   o.y = pack_bf2(a4[2*c].z, a4[2*c].w);
            o.z = pack_bf2(a4[2*c+1].x, a4[2*c+1].y); o.w = pack_bf2(a4[2*c+1].z, a4[2*c+1].w);
            *(uint4*)((unsigned char*)sA[0] + tid * LDA * 2 + c * 16) = o;
        }
    } else {
        #pragma unroll
        for (int c = 0; c < 4; c++) CP_ASYNC16(dA0 + c * 16, srcA + c * 8);
    }
    #pragma unroll
    for (int l = 0; l < 3; l++) CP_ASYNC16(dBb[0] + dBoff[l], srcB[l]);
    CP_COMMIT();

    float4 a4n[8];   // MODE0: staged fp32 A row for next tile

    for (int t = 0; t < T; t++) {
        if (t + 1 < T) {
            const int k0 = (t + 1) * BK;
            const uint32_t dBx = dBb[(t + 1) & 1];
            if constexpr (MODE == 0) {
                #pragma unroll
                for (int c = 0; c < 8; c++) a4n[c] = *(const float4*)(srcA32 + k0 + c * 4);
            } else {
                const uint32_t dAx = ((t + 1) & 1) ? dA1 : dA0;
                #pragma unroll
                for (int c = 0; c < 4; c++) CP_ASYNC16(dAx + c * 16, srcA + k0 + c * 8);
            }
            #pragma unroll
            for (int l = 0; l < 3; l++) CP_ASYNC16(dBx + dBoff[l], srcB[l] + (size_t)k0 * NDIM);
            CP_COMMIT();
            CP_WAIT(1);
        } else {
            CP_WAIT(0);
        }
        __syncthreads();

        const bf16* At = sA[t & 1];
        const bf16* Bt = sB[t & 1];

        #pragma unroll
        for (int kk = 0; kk < BK; kk += 16) {
            wmma::fragment<wmma::matrix_a, 16, 16, 16, bf16, wmma::row_major> af[4];
            wmma::fragment<wmma::matrix_b, 16, 16, 16, bf16, wmma::row_major> bf_[3];
            #pragma unroll
            for (int i = 0; i < 4; i++)
                wmma::load_matrix_sync(af[i], At + (wm * 64 + i * 16) * LDA + kk, LDA);
            #pragma unroll
            for (int j = 0; j < 3; j++)
                wmma::load_matrix_sync(bf_[j], Bt + kk * LDB + wn * 48 + j * 16, LDB);
            #pragma unroll
            for (int i = 0; i < 4; i++)
                #pragma unroll
                for (int j = 0; j < 3; j++)
                    wmma::mma_sync(cf[i][j], af[i], bf_[j], cf[i][j]);
        }
        __syncthreads();

        // MODE0: convert + store staged A row for tile t+1 into the stage that
        // mma(t-1) last read (free since the sync above); visible at next top sync.
        if constexpr (MODE == 0) {
            if (t + 1 < T) {
                unsigned char* dAx = (unsigned char*)sA[(t + 1) & 1] + tid * LDA * 2;
                #pragma unroll
                for (int c = 0; c < 4; c++) {
                    uint4 o;
                    o.x = pack_bf2(a4n[2*c].x, a4n[2*c].y);     o.y = pack_bf2(a4n[2*c].z, a4n[2*c].w);
                    o.z = pack_bf2(a4n[2*c+1].x, a4n[2*c+1].y); o.w = pack_bf2(a4n[2*c+1].z, a4n[2*c+1].w);
                    *(uint4*)(dAx + c * 16) = o;
                }
            }
        }
    }
    if constexpr (MODE == 0) __syncthreads();   // STS of last iter (none) / ensure all mma done before epilogue aliasing

    #pragma unroll
    for (int h = 0; h < 2; h++) {
        if (wm == h) {
            #pragma unroll
            for (int i = 0; i < 4; i++)
                #pragma unroll
                for (int j = 0; j < 3; j++)
                    wmma::store_matrix_sync(sC + (i * 16) * LDC + wn * 48 + j * 16,
                                            cf[i][j], LDC, wmma::mem_row_major);
        }
        __syncthreads();

        const int row  = tid >> 1;
        const int half = tid & 1;
        const int c0   = half * 48;
        const int m    = bm + h * 64 + row;
        float v[48];
        #pragma unroll
        for (int c4 = 0; c4 < 12; c4++) {
            float4 w4 = *(const float4*)(sC + row * LDC + c0 + c4 * 4);
            const int gc = bn + c0 + c4 * 4;
            v[c4*4+0] = w4.x + __ldg(bias + gc + 0);
            v[c4*4+1] = w4.y + __ldg(bias + gc + 1);
            v[c4*4+2] = w4.z + __ldg(bias + gc + 2);
            v[c4*4+3] = w4.w + __ldg(bias + gc + 3);
        }

        if constexpr (MODE == 0) {
            bf16* dst = g_qkv + (size_t)m * QKVN + bn + c0;
            #pragma unroll
            for (int g = 0; g < 6; g++) {
                uint4 o;
                o.x = pack_bf2(v[g*8+0], v[g*8+1]); o.y = pack_bf2(v[g*8+2], v[g*8+3]);
                o.z = pack_bf2(v[g*8+4], v[g*8+5]); o.w = pack_bf2(v[g*8+6], v[g*8+7]);
                *(uint4*)(dst + g * 8) = o;
            }
        } else if constexpr (MODE == 1) {
            const int grow = map_win_to_global(m);
            const size_t o = (size_t)grow * CDIM + bn + c0;
            #pragma unroll
            for (int c4 = 0; c4 < 12; c4++) {
                float4 r = *(const float4*)(resid + o + c4 * 4);
                *(float4*)(g_x1 + o + c4 * 4) =
                    make_float4(v[c4*4+0] + r.x, v[c4*4+1] + r.y, v[c4*4+2] + r.z, v[c4*4+3] + r.w);
            }
        } else if constexpr (MODE == 2) {
            bf16* dst = g_h + (size_t)m * HID + bn + c0;
            #pragma unroll
            for (int g = 0; g < 6; g++) {
                uint4 o;
                o.x = pack_bf2(gelu_exact(v[g*8+0]), gelu_exact(v[g*8+1]));
                o.y = pack_bf2(gelu_exact(v[g*8+2]), gelu_exact(v[g*8+3]));
                o.z = pack_bf2(gelu_exact(v[g*8+4]), gelu_exact(v[g*8+5]));
                o.w = pack_bf2(gelu_exact(v[g*8+6]), gelu_exact(v[g*8+7]));
                *(uint4*)(dst + g * 8) = o;
            }
        } else {
            const size_t o = (size_t)m * CDIM + bn + c0;
            #pragma unroll
            for (int c4 = 0; c4 < 12; c4++) {
                float4 r = *(const float4*)(g_x1 + o + c4 * 4);
                *(float4*)(Cout + o + c4 * 4) =
                    make_float4(v[c4*4+0] + r.x, v[c4*4+1] + r.y, v[c4*4+2] + r.z, v[c4*4+3] + r.w);
            }
        }
        __syncthreads();
    }
}

// ---------------- LayerNorm: one warp per token, bf16 out ---------------------
__global__ void __launch_bounds__(256) ln_norm_k(const float* __restrict__ gamma,
                                                 const float* __restrict__ beta)
{
    const int r = blockIdx.x * 8 + (threadIdx.x >> 5);
    const int lane = threadIdx.x & 31;
    const float* p = g_x1 + (size_t)r * CDIM;
    float v[6];
    float s = 0.f, ss = 0.f;
    #pragma unroll
    for (int k = 0; k < 6; k++) {
        v[k] = p[lane + k * 32];
        s += v[k]; ss += v[k] * v[k];
    }
    #pragma unroll
    for (int o = 16; o; o >>= 1) {
        s  += __shfl_xor_sync(0xffffffffu, s,  o);
        ss += __shfl_xor_sync(0xffffffffu, ss, o);
    }
    const float mu = s * (1.f / 192.f);
    const float var = ss * (1.f / 192.f) - mu * mu;
    const float rs = rsqrtf(var + 1e-5f);
    bf16* q = g_x1n + (size_t)r * CDIM;
    #pragma unroll
    for (int k = 0; k < 6; k++) {
        const int c = lane + k * 32;
        q[c] = __float2bfloat16_rn((v[k] - mu) * rs * __ldg(gamma + c) + __ldg(beta + c));
    }
}

// ---------------- attention: register-resident S, trans-ldmatrix V (R14) ------
#define ALQ 40     // sQ/sK/sV row stride (bf16)

__global__ void __launch_bounds__(128) attn_tc(const float* __restrict__ rpb)
{
    const int w = blockIdx.x, head = blockIdx.y;
    const int tid = threadIdx.x;
    const int wid = tid >> 5, lane = tid & 31;

    __shared__ __align__(16) bf16 sQ[64 * ALQ];
    __shared__ __align__(16) bf16 sK[64 * ALQ];
    __shared__ __align__(16) bf16 sV[64 * ALQ];
    __shared__ float sRp[225];
    __shared__ int   sReg[64];

    const bf16* base = g_qkv + (size_t)w * 64 * QKVN + head * 32;
    #pragma unroll
    for (int l = 0; l < 2; l++) {
        int i = tid + l * 128;
        int row = i >> 2, cg = (i & 3) * 8;
        const bf16* src = base + (size_t)row * QKVN;
        *(uint4*)(sQ + row * ALQ + cg) = *(const uint4*)(src + cg);
        *(uint4*)(sK + row * ALQ + cg) = *(const uint4*)(src + CDIM + cg);
        *(uint4*)(sV + row * ALQ + cg) = *(const uint4*)(src + 2 * CDIM + cg);
    }
    for (int i = tid; i < 225; i += 128) sRp[i] = rpb[i * NHEAD + head];
    if (tid < 64) {
        int rem = w & 255; int wh = rem >> 4, ww = rem & 15;
        int hs  = wh * 8 + (tid >> 3);
        int wsc = ww * 8 + (tid & 7);
        int rh = hs  < 120 ? 0 : (hs  < 124 ? 1 : 2);
        int rw = wsc < 120 ? 0 : (wsc < 124 ? 1 : 2);
        sReg[tid] = rh * 3 + rw;
    }
    __syncthreads();

    const int r0 = wid * 16;
    const int qr = lane >> 2;
    const int qc = lane & 3;
    const uint32_t sQa = smem_u32(sQ), sKa = smem_u32(sK), sVa = smem_u32(sV);

    uint32_t aq[2][4];
    #pragma unroll
    for (int kk = 0; kk < 2; kk++) {
        uint32_t addr = sQa + (uint32_t)((r0 + (lane & 15)) * ALQ * 2 + kk * 32 + (lane >> 4) * 16);
        LDMATRIX_X4(aq[kk][0], aq[kk][1], aq[kk][2], aq[kk][3], addr);
    }

    float acc[8][4];
    #pragma unroll
    for (int nb = 0; nb < 8; nb++) {
        acc[nb][0] = acc[nb][1] = acc[nb][2] = acc[nb][3] = 0.f;
        uint32_t kb0, kb1, kb2, kb3;
        uint32_t addr = sKa + (uint32_t)((8 * nb + (lane & 7)) * ALQ * 2 + (lane >> 3) * 16);
        LDMATRIX_X4(kb0, kb1, kb2, kb3, addr);
        MMA_16816(acc[nb], aq[0], kb0, kb1);
        MMA_16816(acc[nb], aq[1], kb2, kb3);
    }

    const int grow0 = r0 + qr, grow1 = grow0 + 8;
    const int i10 = grow0 >> 3, j10 = grow0 & 7, reg0 = sReg[grow0];
    const int i11 = grow1 >> 3, j11 = grow1 & 7, reg1 = sReg[grow1];
    const float scale = 0.17677669529663689f;
    float sum0 = 0.f, sum1 = 0.f;
    #pragma unroll
    for (int nb = 0; nb < 8; nb++) {
        #pragma unroll
        for (int e = 0; e < 2; e++) {
            const int c = 8 * nb + 2 * qc + e;
            const int j2 = c & 7;
            const int rc = sReg[c];
            const float m0 = (rc == reg0) ? 0.f : -100.f;
            const float m1 = (rc == reg1) ? 0.f : -100.f;
            const float b0 = sRp[(i10 - nb + 7) * 15 + (j10 - j2 + 7)];
            const float b1 = sRp[(i11 - nb + 7) * 15 + (j11 - j2 + 7)];
            float e0 = __expf(acc[nb][e]     * scale + b0 + m0);
            float e1 = __expf(acc[nb][2 + e] * scale + b1 + m1);
            acc[nb][e] = e0;     sum0 += e0;
            acc[nb][2 + e] = e1; sum1 += e1;
        }
    }
    sum0 += __shfl_xor_sync(0xffffffffu, sum0, 1);
    sum0 += __shfl_xor_sync(0xffffffffu, sum0, 2);
    sum1 += __shfl_xor_sync(0xffffffffu, sum1, 1);
    sum1 += __shfl_xor_sync(0xffffffffu, sum1, 2);
    const float inv0 = 1.f / sum0, inv1 = 1.f / sum1;

    uint32_t pa[4][4];
    #pragma unroll
    for (int kk = 0; kk < 4; kk++) {
        const int na = 2 * kk, nbb = 2 * kk + 1;
        pa[kk][0] = pack_bf2(acc[na][0] * inv0, acc[na][1] * inv0);
        pa[kk][1] = pack_bf2(acc[na][2] * inv1, acc[na][3] * inv1);
        pa[kk][2] = pack_bf2(acc[nbb][0] * inv0, acc[nbb][1] * inv0);
        pa[kk][3] = pack_bf2(acc[nbb][2] * inv1, acc[nbb][3] * inv1);
    }

    float oacc[4][4];
    #pragma unroll
    for (int nd = 0; nd < 4; nd++) {
        oacc[nd][0] = oacc[nd][1] = oacc[nd][2] = oacc[nd][3] = 0.f;
        uint32_t vb0, vb1, vb2, vb3;
        uint32_t addr = sVa + (uint32_t)(lane * ALQ * 2 + nd * 16);
        LDMATRIX_X4_T(vb0, vb1, vb2, vb3, addr);                 // keys 0..31
        MMA_16816(oacc[nd], pa[0], vb0, vb1);
        MMA_16816(oacc[nd], pa[1], vb2, vb3);
        addr = sVa + (uint32_t)((32 + lane) * ALQ * 2 + nd * 16);
        LDMATRIX_X4_T(vb0, vb1, vb2, vb3, addr);                 // keys 32..63
        MMA_16816(oacc[nd], pa[2], vb0, vb1);
        MMA_16816(oacc[nd], pa[3], vb2, vb3);
    }

    bf16* op0 = g_attnout + ((size_t)(w * 64 + grow0)) * CDIM + head * 32 + 2 * qc;
    bf16* op1 = g_attnout + ((size_t)(w * 64 + grow1)) * CDIM + head * 32 + 2 * qc;
    #pragma unroll
    for (int nd = 0; nd < 4; nd++) {
        *(uint32_t*)(op0 + 8 * nd) = pack_bf2(oacc[nd][0], oacc[nd][1]);
        *(uint32_t*)(op1 + 8 * nd) = pack_bf2(oacc[nd][2], oacc[nd][3]);
    }
}

// ---------------- launch -----------------------------------------------------
extern "C" void kernel_launch(void* const* d_in, const int* in_sizes, int n_in,
                              void* d_out, int out_size)
{
    const float* x       = (const float*)d_in[0];
    const float* qkv_w   = (const float*)d_in[1];
    const float* qkv_b   = (const float*)d_in[2];
    const float* proj_w  = (const float*)d_in[3];
    const float* proj_b  = (const float*)d_in[4];
    const float* rpb     = (const float*)d_in[5];
    const float* norm2_g = (const float*)d_in[6];
    const float* norm2_b = (const float*)d_in[7];
    const float* mlp_w1  = (const float*)d_in[8];
    const float* mlp_b1  = (const float*)d_in[9];
    const float* mlp_w2  = (const float*)d_in[10];
    const float* mlp_b2  = (const float*)d_in[11];
    float* out = (float*)d_out;

    // weight precision conversion (x conversion fused into QKV GEMM)
    conv_w_all<<<(S0 + S1 + S2 + S3) / (256 * 8), 256>>>(qkv_w, proj_w, mlp_w1, mlp_w2);

    // 1) QKV = gather(x fp32 -> bf16) @ qkv_w + b  -> bf16 g_qkv (window order)
    gemm_bf<192, 576, 0><<<dim3(6, 1024), 128>>>(x, qkv_b, nullptr, nullptr);
    // 2) windowed attention (register-resident softmax) -> bf16 g_attnout
    attn_tc<<<dim3(NWIN, NHEAD), 128>>>(rpb);
    // 3) proj + scatter + residual -> fp32 g_x1
    gemm_bf<192, 192, 1><<<dim3(2, 1024), 128>>>(nullptr, proj_b, x, nullptr);
    // 4) LayerNorm(g_x1) -> bf16 g_x1n
    ln_norm_k<<<TOK / 8, 256>>>(norm2_g, norm2_b);
    // 5) fc1 + GELU -> bf16 g_h
    gemm_bf<192, 768, 2><<<dim3(8, 1024), 128>>>(nullptr, mlp_b1, nullptr, nullptr);
    // 6) fc2 + residual -> fp32 out
    gemm_bf<768, 192, 3><<<dim3(2, 1024), 128>>>(nullptr, mlp_b2, nullptr, out);
}

// round 16
// speedup vs baseline: 1.0716x; 1.0716x over previous
#include <cuda_runtime.h>
#include <cuda_bf16.h>
#include <mma.h>
#include <cstdint>
#include <math.h>

using namespace nvcuda;
typedef __nv_bfloat16 bf16;

// Problem constants (fixed shapes)
#define TOK   131072      // B*H*W = 8*128*128
#define CDIM  192
#define HID   768
#define QKVN  576
#define NHEAD 6
#define SS    4
#define NWIN  2048        // B * 16 * 16

// GEMM tiling: block 128x96 BK=32 (proven tile), now 8 warps (4m x 2n), wtile 32x48
#define BM 128
#define BN 96
#define BK 32
#define LDA 40            // bf16 ld, 80B rows
#define LDB 104           // bf16 ld for B (96+8)
#define LDC 100           // fp32 ld for C half-tile
#define A_STAGE_B (BM * LDA * 2)      // 10240 B
#define B_STAGE_B (BK * LDB * 2)      // 6656 B
#define STAGE_B   (A_STAGE_B + B_STAGE_B)
#define SMEM_BYTES (2 * STAGE_B)      // 33792; C half-tile 64*100*4=25600 fits

// ---------------- scratch (device globals; no allocations allowed) ----------
__device__ bf16  g_xbf[TOK * CDIM];
__device__ bf16  g_qkv[TOK * QKVN];        // window-ordered, bf16
__device__ bf16  g_attnout[TOK * CDIM];    // window-ordered, bf16
__device__ float g_x1[TOK * CDIM];         // fp32 residual spine
__device__ bf16  g_x1n[TOK * CDIM];
__device__ bf16  g_h[TOK * HID];
__device__ bf16  g_wqkv[CDIM * QKVN];
__device__ bf16  g_wproj[CDIM * CDIM];
__device__ bf16  g_w1[CDIM * HID];
__device__ bf16  g_w2[HID * CDIM];

// ---------------- helpers ----------------------------------------------------
__device__ __forceinline__ uint32_t smem_u32(const void* p) {
    uint32_t a;
    asm("{ .reg .u64 t; cvta.to.shared.u64 t, %1; cvt.u32.u64 %0, t; }" : "=r"(a) : "l"(p));
    return a;
}
#define CP_ASYNC16(dst, src) \
    asm volatile("cp.async.cg.shared.global [%0], [%1], 16;" :: "r"(dst), "l"(src))
#define CP_COMMIT() asm volatile("cp.async.commit_group;" ::: "memory")
#define CP_WAIT(n)  asm volatile("cp.async.wait_group %0;" :: "n"(n) : "memory")

#define LDMATRIX_X4(r0, r1, r2, r3, addr) \
    asm volatile("ldmatrix.sync.aligned.m8n8.x4.shared.b16 {%0,%1,%2,%3}, [%4];" \
                 : "=r"(r0), "=r"(r1), "=r"(r2), "=r"(r3) : "r"(addr))
#define LDMATRIX_X4_T(r0, r1, r2, r3, addr) \
    asm volatile("ldmatrix.sync.aligned.m8n8.x4.trans.shared.b16 {%0,%1,%2,%3}, [%4];" \
                 : "=r"(r0), "=r"(r1), "=r"(r2), "=r"(r3) : "r"(addr))

#define MMA_16816(d, a, b0v, b1v) \
    asm volatile("mma.sync.aligned.m16n8k16.row.col.f32.bf16.bf16.f32 " \
                 "{%0,%1,%2,%3}, {%4,%5,%6,%7}, {%8,%9}, {%0,%1,%2,%3};" \
                 : "+f"((d)[0]), "+f"((d)[1]), "+f"((d)[2]), "+f"((d)[3]) \
                 : "r"((a)[0]), "r"((a)[1]), "r"((a)[2]), "r"((a)[3]), \
                   "r"(b0v), "r"(b1v))

__device__ __forceinline__ int map_win_to_global(int r) {
    int w = r >> 6, n = r & 63;
    int b = w >> 8, rem = w & 255;
    int wh = rem >> 4, ww = rem & 15;
    int i = n >> 3, j = n & 7;
    int h  = (wh * 8 + i + SS) & 127;
    int wc = (ww * 8 + j + SS) & 127;
    return (b << 14) + (h << 7) + wc;
}
__device__ __forceinline__ float gelu_exact(float v) {
    return 0.5f * v * (1.0f + erff(v * 0.70710678118654752440f));
}
__device__ __forceinline__ uint32_t pack_bf2(float a, float b) {
    __nv_bfloat162 h = __floats2bfloat162_rn(a, b);
    return *(uint32_t*)&h;
}

// ---------------- fp32 -> bf16 conversion -------------------------------------
__global__ void __launch_bounds__(256) conv_x_k(const float* __restrict__ src) {
    const size_t i = ((size_t)blockIdx.x * 256 + threadIdx.x) * 8;
    float4 v0 = *(const float4*)(src + i);
    float4 v1 = *(const float4*)(src + i + 4);
    uint4 o;
    o.x = pack_bf2(v0.x, v0.y); o.y = pack_bf2(v0.z, v0.w);
    o.z = pack_bf2(v1.x, v1.y); o.w = pack_bf2(v1.z, v1.w);
    *(uint4*)(g_xbf + i) = o;
}
#define S0 (CDIM*QKVN)
#define S1 (CDIM*CDIM)
#define S2 (CDIM*HID)
#define S3 (HID*CDIM)
__global__ void __launch_bounds__(256) conv_w_all(
    const float* __restrict__ w0, const float* __restrict__ w1,
    const float* __restrict__ w2, const float* __restrict__ w3)
{
    const int off = (blockIdx.x * 256 + threadIdx.x) * 8;
    const float* src; bf16* dst; int lo;
    if      (off < S0)            { src = w0; dst = g_wqkv;  lo = off; }
    else if (off < S0+S1)         { src = w1; dst = g_wproj; lo = off - S0; }
    else if (off < S0+S1+S2)      { src = w2; dst = g_w1;    lo = off - S0 - S1; }
    else if (off < S0+S1+S2+S3)   { src = w3; dst = g_w2;    lo = off - S0 - S1 - S2; }
    else return;
    float4 v0 = *(const float4*)(src + lo);
    float4 v1 = *(const float4*)(src + lo + 4);
    uint4 o;
    o.x = pack_bf2(v0.x, v0.y); o.y = pack_bf2(v0.z, v0.w);
    o.z = pack_bf2(v1.x, v1.y); o.w = pack_bf2(v1.z, v1.w);
    *(uint4*)(dst + lo) = o;
}

// ---------------- WMMA bf16 GEMM: 128x96, 8 warps (4m x 2n), wtile 32x48 ------
// MODE: 0=QKV(gather A; out bf16 g_qkv)  1=PROJ(scatter+resid -> fp32 g_x1)
//       2=FC1(gelu -> bf16 g_h)          3=FC2(+resid g_x1 -> fp32 Cout)
template<int KDIM, int NDIM, int MODE>
__global__ void __launch_bounds__(256, 2) gemm_bf(
    const float* __restrict__ bias,
    const float* __restrict__ resid,
    float* __restrict__ Cout)
{
    __shared__ __align__(16) unsigned char smem[SMEM_BYTES];
    bf16* sA[2] = { (bf16*)smem, (bf16*)(smem + STAGE_B) };
    bf16* sB[2] = { (bf16*)(smem + A_STAGE_B), (bf16*)(smem + STAGE_B + A_STAGE_B) };
    float* sC = (float*)smem;

    const int tid = threadIdx.x;
    const int bm = blockIdx.y * BM;
    const int bn = blockIdx.x * BN;

    const bf16* Aptr;
    const bf16* Bptr;
    if      constexpr (MODE == 0) { Aptr = g_xbf;     Bptr = g_wqkv; }
    else if constexpr (MODE == 1) { Aptr = g_attnout; Bptr = g_wproj; }
    else if constexpr (MODE == 2) { Aptr = g_x1n;     Bptr = g_w1; }
    else                          { Aptr = g_h;       Bptr = g_w2; }

    // A: thread owns half-row (16 bf16 = 2 x 16B)
    const int aRow = tid >> 1, aHalf = tid & 1;
    int grA;
    if constexpr (MODE == 0) grA = map_win_to_global(bm + aRow);
    else                     grA = bm + aRow;
    const bf16* srcA = Aptr + (size_t)grA * KDIM + aHalf * 16;
    const uint32_t dAoff = (uint32_t)((aRow * LDA + aHalf * 16) * 2);
    const uint32_t dAb[2] = { smem_u32(sA[0]) + dAoff, smem_u32(sA[1]) + dAoff };

    // B: 32 rows x 96 bf16 = 384 x 8-elem chunks; chunk tid always, chunk tid+256 if tid<128
    const int bR0 = tid / 12,        bC0 = (tid % 12) * 8;
    const int idx1 = tid + 256;
    const int bR1 = idx1 / 12,       bC1 = (idx1 % 12) * 8;
    const bool hasB1 = (tid < 128);
    const bf16* srcB0 = Bptr + (size_t)bR0 * NDIM + bn + bC0;
    const bf16* srcB1 = Bptr + (size_t)bR1 * NDIM + bn + bC1;
    const uint32_t dB0off = (uint32_t)((bR0 * LDB + bC0) * 2);
    const uint32_t dB1off = (uint32_t)((bR1 * LDB + bC1) * 2);
    const uint32_t dBb[2] = { smem_u32(sB[0]), smem_u32(sB[1]) };

    constexpr int T = KDIM / BK;
    const int wid = tid >> 5;
    const int wm = wid & 3, wn = wid >> 2;   // 4m x 2n, warp tile 32x48

    wmma::fragment<wmma::accumulator, 16, 16, 16, float> cf[2][3];
    #pragma unroll
    for (int i = 0; i < 2; i++)
        #pragma unroll
        for (int j = 0; j < 3; j++) wmma::fill_fragment(cf[i][j], 0.0f);

    // prologue: stage 0
    CP_ASYNC16(dAb[0],      srcA);
    CP_ASYNC16(dAb[0] + 16, srcA + 8);
    CP_ASYNC16(dBb[0] + dB0off, srcB0);
    if (hasB1) CP_ASYNC16(dBb[0] + dB1off, srcB1);
    CP_COMMIT();

    for (int t = 0; t < T; t++) {
        if (t + 1 < T) {
            const int k0 = (t + 1) * BK;
            const int st = (t + 1) & 1;
            CP_ASYNC16(dAb[st],      srcA + k0);
            CP_ASYNC16(dAb[st] + 16, srcA + k0 + 8);
            CP_ASYNC16(dBb[st] + dB0off, srcB0 + (size_t)k0 * NDIM);
            if (hasB1) CP_ASYNC16(dBb[st] + dB1off, srcB1 + (size_t)k0 * NDIM);
            CP_COMMIT();
            CP_WAIT(1);
        } else {
            CP_WAIT(0);
        }
        __syncthreads();

        const bf16* At = sA[t & 1];
        const bf16* Bt = sB[t & 1];

        #pragma unroll
        for (int kk = 0; kk < BK; kk += 16) {
            wmma::fragment<wmma::matrix_a, 16, 16, 16, bf16, wmma::row_major> af[2];
            wmma::fragment<wmma::matrix_b, 16, 16, 16, bf16, wmma::row_major> bf_[3];
            #pragma unroll
            for (int i = 0; i < 2; i++)
                wmma::load_matrix_sync(af[i], At + (wm * 32 + i * 16) * LDA + kk, LDA);
            #pragma unroll
            for (int j = 0; j < 3; j++)
                wmma::load_matrix_sync(bf_[j], Bt + kk * LDB + wn * 48 + j * 16, LDB);
            #pragma unroll
            for (int i = 0; i < 2; i++)
                #pragma unroll
                for (int j = 0; j < 3; j++)
                    wmma::mma_sync(cf[i][j], af[i], bf_[j], cf[i][j]);
        }
        __syncthreads();
    }

    // ---------------- epilogue: two 64-row passes ------------------------------
    #pragma unroll
    for (int h = 0; h < 2; h++) {
        if ((wm >> 1) == h) {
            const int rbase = (wm & 1) * 32;
            #pragma unroll
            for (int i = 0; i < 2; i++)
                #pragma unroll
                for (int j = 0; j < 3; j++)
                    wmma::store_matrix_sync(sC + (rbase + i * 16) * LDC + wn * 48 + j * 16,
                                            cf[i][j], LDC, wmma::mem_row_major);
        }
        __syncthreads();

        // 64 rows x 96 cols; thread owns (row = tid>>2, q = tid&3 -> 24 cols)
        const int row = tid >> 2;
        const int q   = tid & 3;
        const int c0  = q * 24;
        const int m   = bm + h * 64 + row;
        float v[24];
        #pragma unroll
        for (int c4 = 0; c4 < 6; c4++) {
            float4 w4 = *(const float4*)(sC + row * LDC + c0 + c4 * 4);
            const int gc = bn + c0 + c4 * 4;
            v[c4*4+0] = w4.x + __ldg(bias + gc + 0);
            v[c4*4+1] = w4.y + __ldg(bias + gc + 1);
            v[c4*4+2] = w4.z + __ldg(bias + gc + 2);
            v[c4*4+3] = w4.w + __ldg(bias + gc + 3);
        }

        if constexpr (MODE == 0) {
            bf16* dst = g_qkv + (size_t)m * QKVN + bn + c0;
            #pragma unroll
            for (int g = 0; g < 3; g++) {
                uint4 o;
                o.x = pack_bf2(v[g*8+0], v[g*8+1]); o.y = pack_bf2(v[g*8+2], v[g*8+3]);
                o.z = pack_bf2(v[g*8+4], v[g*8+5]); o.w = pack_bf2(v[g*8+6], v[g*8+7]);
                *(uint4*)(dst + g * 8) = o;
            }
        } else if constexpr (MODE == 1) {
            const int grow = map_win_to_global(m);
            const size_t o = (size_t)grow * CDIM + bn + c0;
            #pragma unroll
            for (int c4 = 0; c4 < 6; c4++) {
                float4 r = *(const float4*)(resid + o + c4 * 4);
                *(float4*)(g_x1 + o + c4 * 4) =
                    make_float4(v[c4*4+0] + r.x, v[c4*4+1] + r.y, v[c4*4+2] + r.z, v[c4*4+3] + r.w);
            }
        } else if constexpr (MODE == 2) {
            bf16* dst = g_h + (size_t)m * HID + bn + c0;
            #pragma unroll
            for (int g = 0; g < 3; g++) {
                uint4 o;
                o.x = pack_bf2(gelu_exact(v[g*8+0]), gelu_exact(v[g*8+1]));
                o.y = pack_bf2(gelu_exact(v[g*8+2]), gelu_exact(v[g*8+3]));
                o.z = pack_bf2(gelu_exact(v[g*8+4]), gelu_exact(v[g*8+5]));
                o.w = pack_bf2(gelu_exact(v[g*8+6]), gelu_exact(v[g*8+7]));
                *(uint4*)(dst + g * 8) = o;
            }
        } else {
            const size_t o = (size_t)m * CDIM + bn + c0;
            #pragma unroll
            for (int c4 = 0; c4 < 6; c4++) {
                float4 r = *(const float4*)(g_x1 + o + c4 * 4);
                *(float4*)(Cout + o + c4 * 4) =
                    make_float4(v[c4*4+0] + r.x, v[c4*4+1] + r.y, v[c4*4+2] + r.z, v[c4*4+3] + r.w);
            }
        }
        __syncthreads();
    }
}

// ---------------- LayerNorm: one warp per token, bf16 out ---------------------
__global__ void __launch_bounds__(256) ln_norm_k(const float* __restrict__ gamma,
                                                 const float* __restrict__ beta)
{
    const int r = blockIdx.x * 8 + (threadIdx.x >> 5);
    const int lane = threadIdx.x & 31;
    const float* p = g_x1 + (size_t)r * CDIM;
    float v[6];
    float s = 0.f, ss = 0.f;
    #pragma unroll
    for (int k = 0; k < 6; k++) {
        v[k] = p[lane + k * 32];
        s += v[k]; ss += v[k] * v[k];
    }
    #pragma unroll
    for (int o = 16; o; o >>= 1) {
        s  += __shfl_xor_sync(0xffffffffu, s,  o);
        ss += __shfl_xor_sync(0xffffffffu, ss, o);
    }
    const float mu = s * (1.f / 192.f);
    const float var = ss * (1.f / 192.f) - mu * mu;
    const float rs = rsqrtf(var + 1e-5f);
    bf16* q = g_x1n + (size_t)r * CDIM;
    #pragma unroll
    for (int k = 0; k < 6; k++) {
        const int c = lane + k * 32;
        q[c] = __float2bfloat16_rn((v[k] - mu) * rs * __ldg(gamma + c) + __ldg(beta + c));
    }
}

// ---------------- attention: register-resident S, trans-ldmatrix V (R14) ------
#define ALQ 40     // sQ/sK/sV row stride (bf16)

__global__ void __launch_bounds__(128) attn_tc(const float* __restrict__ rpb)
{
    const int w = blockIdx.x, head = blockIdx.y;
    const int tid = threadIdx.x;
    const int wid = tid >> 5, lane = tid & 31;

    __shared__ __align__(16) bf16 sQ[64 * ALQ];
    __shared__ __align__(16) bf16 sK[64 * ALQ];
    __shared__ __align__(16) bf16 sV[64 * ALQ];
    __shared__ float sRp[225];
    __shared__ int   sReg[64];

    const bf16* base = g_qkv + (size_t)w * 64 * QKVN + head * 32;
    #pragma unroll
    for (int l = 0; l < 2; l++) {
        int i = tid + l * 128;
        int row = i >> 2, cg = (i & 3) * 8;
        const bf16* src = base + (size_t)row * QKVN;
        *(uint4*)(sQ + row * ALQ + cg) = *(const uint4*)(src + cg);
        *(uint4*)(sK + row * ALQ + cg) = *(const uint4*)(src + CDIM + cg);
        *(uint4*)(sV + row * ALQ + cg) = *(const uint4*)(src + 2 * CDIM + cg);
    }
    for (int i = tid; i < 225; i += 128) sRp[i] = rpb[i * NHEAD + head];
    if (tid < 64) {
        int rem = w & 255; int wh = rem >> 4, ww = rem & 15;
        int hs  = wh * 8 + (tid >> 3);
        int wsc = ww * 8 + (tid & 7);
        int rh = hs  < 120 ? 0 : (hs  < 124 ? 1 : 2);
        int rw = wsc < 120 ? 0 : (wsc < 124 ? 1 : 2);
        sReg[tid] = rh * 3 + rw;
    }
    __syncthreads();

    const int r0 = wid * 16;
    const int qr = lane >> 2;
    const int qc = lane & 3;
    const uint32_t sQa = smem_u32(sQ), sKa = smem_u32(sK), sVa = smem_u32(sV);

    uint32_t aq[2][4];
    #pragma unroll
    for (int kk = 0; kk < 2; kk++) {
        uint32_t addr = sQa + (uint32_t)((r0 + (lane & 15)) * ALQ * 2 + kk * 32 + (lane >> 4) * 16);
        LDMATRIX_X4(aq[kk][0], aq[kk][1], aq[kk][2], aq[kk][3], addr);
    }

    float acc[8][4];
    #pragma unroll
    for (int nb = 0; nb < 8; nb++) {
        acc[nb][0] = acc[nb][1] = acc[nb][2] = acc[nb][3] = 0.f;
        uint32_t kb0, kb1, kb2, kb3;
        uint32_t addr = sKa + (uint32_t)((8 * nb + (lane & 7)) * ALQ * 2 + (lane >> 3) * 16);
        LDMATRIX_X4(kb0, kb1, kb2, kb3, addr);
        MMA_16816(acc[nb], aq[0], kb0, kb1);
        MMA_16816(acc[nb], aq[1], kb2, kb3);
    }

    const int grow0 = r0 + qr, grow1 = grow0 + 8;
    const int i10 = grow0 >> 3, j10 = grow0 & 7, reg0 = sReg[grow0];
    const int i11 = grow1 >> 3, j11 = grow1 & 7, reg1 = sReg[grow1];
    const float scale = 0.17677669529663689f;
    float sum0 = 0.f, sum1 = 0.f;
    #pragma unroll
    for (int nb = 0; nb < 8; nb++) {
        #pragma unroll
        for (int e = 0; e < 2; e++) {
            const int c = 8 * nb + 2 * qc + e;
            const int j2 = c & 7;
            const int rc = sReg[c];
            const float m0 = (rc == reg0) ? 0.f : -100.f;
            const float m1 = (rc == reg1) ? 0.f : -100.f;
            const float b0 = sRp[(i10 - nb + 7) * 15 + (j10 - j2 + 7)];
            const float b1 = sRp[(i11 - nb + 7) * 15 + (j11 - j2 + 7)];
            float e0 = __expf(acc[nb][e]     * scale + b0 + m0);
            float e1 = __expf(acc[nb][2 + e] * scale + b1 + m1);
            acc[nb][e] = e0;     sum0 += e0;
            acc[nb][2 + e] = e1; sum1 += e1;
        }
    }
    sum0 += __shfl_xor_sync(0xffffffffu, sum0, 1);
    sum0 += __shfl_xor_sync(0xffffffffu, sum0, 2);
    sum1 += __shfl_xor_sync(0xffffffffu, sum1, 1);
    sum1 += __shfl_xor_sync(0xffffffffu, sum1, 2);
    const float inv0 = 1.f / sum0, inv1 = 1.f / sum1;

    uint32_t pa[4][4];
    #pragma unroll
    for (int kk = 0; kk < 4; kk++) {
        const int na = 2 * kk, nbb = 2 * kk + 1;
        pa[kk][0] = pack_bf2(acc[na][0] * inv0, acc[na][1] * inv0);
        pa[kk][1] = pack_bf2(acc[na][2] * inv1, acc[na][3] * inv1);
        pa[kk][2] = pack_bf2(acc[nbb][0] * inv0, acc[nbb][1] * inv0);
        pa[kk][3] = pack_bf2(acc[nbb][2] * inv1, acc[nbb][3] * inv1);
    }

    float oacc[4][4];
    #pragma unroll
    for (int nd = 0; nd < 4; nd++) {
        oacc[nd][0] = oacc[nd][1] = oacc[nd][2] = oacc[nd][3] = 0.f;
        uint32_t vb0, vb1, vb2, vb3;
        uint32_t addr = sVa + (uint32_t)(lane * ALQ * 2 + nd * 16);
        LDMATRIX_X4_T(vb0, vb1, vb2, vb3, addr);                 // keys 0..31
        MMA_16816(oacc[nd], pa[0], vb0, vb1);
        MMA_16816(oacc[nd], pa[1], vb2, vb3);
        addr = sVa + (uint32_t)((32 + lane) * ALQ * 2 + nd * 16);
        LDMATRIX_X4_T(vb0, vb1, vb2, vb3, addr);                 // keys 32..63
        MMA_16816(oacc[nd], pa[2], vb0, vb1);
        MMA_16816(oacc[nd], pa[3], vb2, vb3);
    }

    bf16* op0 = g_attnout + ((size_t)(w * 64 + grow0)) * CDIM + head * 32 + 2 * qc;
    bf16* op1 = g_attnout + ((size_t)(w * 64 + grow1)) * CDIM + head * 32 + 2 * qc;
    #pragma unroll
    for (int nd = 0; nd < 4; nd++) {
        *(uint32_t*)(op0 + 8 * nd) = pack_bf2(oacc[nd][0], oacc[nd][1]);
        *(uint32_t*)(op1 + 8 * nd) = pack_bf2(oacc[nd][2], oacc[nd][3]);
    }
}

// ---------------- launch -----------------------------------------------------
extern "C" void kernel_launch(void* const* d_in, const int* in_sizes, int n_in,
                              void* d_out, int out_size)
{
    const float* x       = (const float*)d_in[0];
    const float* qkv_w   = (const float*)d_in[1];
    const float* qkv_b   = (const float*)d_in[2];
    const float* proj_w  = (const float*)d_in[3];
    const float* proj_b  = (const float*)d_in[4];
    const float* rpb     = (const float*)d_in[5];
    const float* norm2_g = (const float*)d_in[6];
    const float* norm2_b = (const float*)d_in[7];
    const float* mlp_w1  = (const float*)d_in[8];
    const float* mlp_b1  = (const float*)d_in[9];
    const float* mlp_w2  = (const float*)d_in[10];
    const float* mlp_b2  = (const float*)d_in[11];
    float* out = (float*)d_out;

    // precision conversions
    conv_x_k<<<TOK * CDIM / (256 * 8), 256>>>(x);
    conv_w_all<<<(S0 + S1 + S2 + S3) / (256 * 8), 256>>>(qkv_w, proj_w, mlp_w1, mlp_w2);

    // 1) QKV = gather(x) @ qkv_w + b  -> bf16 g_qkv (window order)
    gemm_bf<192, 576, 0><<<dim3(6, 1024), 256>>>(qkv_b, nullptr, nullptr);
    // 2) windowed attention (register-resident softmax) -> bf16 g_attnout
    attn_tc<<<dim3(NWIN, NHEAD), 128>>>(rpb);
    // 3) proj + scatter + residual -> fp32 g_x1
    gemm_bf<192, 192, 1><<<dim3(2, 1024), 256>>>(proj_b, x, nullptr);
    // 4) LayerNorm(g_x1) -> bf16 g_x1n
    ln_norm_k<<<TOK / 8, 256>>>(norm2_g, norm2_b);
    // 5) fc1 + GELU -> bf16 g_h
    gemm_bf<192, 768, 2><<<dim3(8, 1024), 256>>>(mlp_b1, nullptr, nullptr);
    // 6) fc2 + residual -> fp32 out
    gemm_bf<768, 192, 3><<<dim3(2, 1024), 256>>>(mlp_b2, nullptr, out);
}

// round 17
// speedup vs baseline: 1.1035x; 1.0297x over previous
#include <cuda_runtime.h>
#include <cuda_bf16.h>
#include <mma.h>
#include <cstdint>
#include <math.h>

using namespace nvcuda;
typedef __nv_bfloat16 bf16;

// Problem constants (fixed shapes)
#define TOK   131072      // B*H*W = 8*128*128
#define CDIM  192
#define HID   768
#define QKVN  576
#define NHEAD 6
#define SS    4
#define NWIN  2048        // B * 16 * 16

// GEMM tiling: block 128x96, 4 warps (2m x 2n), warp tile 64x48  (R14 proven)
#define BM 128
#define BN 96
#define BK 32
#define LDA 40            // bf16 ld, 80B rows
#define LDB 104           // bf16 ld for B (96+8)
#define LDC 100           // fp32 ld for C half-tile
#define A_STAGE_B (BM * LDA * 2)      // 10240 B
#define B_STAGE_B (BK * LDB * 2)      // 6656 B
#define STAGE_B   (A_STAGE_B + B_STAGE_B)
#define SMEM_BYTES (2 * STAGE_B)      // 33792; C half-tile 64*100*4=25600 fits

// ---------------- scratch (device globals; no allocations allowed) ----------
__device__ bf16  g_xbf[TOK * CDIM];
__device__ bf16  g_qkv[TOK * QKVN];        // window-ordered, bf16
__device__ bf16  g_attnout[TOK * CDIM];    // window-ordered, bf16
__device__ float g_x1[TOK * CDIM];         // fp32 residual spine
__device__ bf16  g_x1n[TOK * CDIM];
__device__ bf16  g_h[TOK * HID];
__device__ bf16  g_wqkv[CDIM * QKVN];
__device__ bf16  g_wproj[CDIM * CDIM];
__device__ bf16  g_w1[CDIM * HID];
__device__ bf16  g_w2[HID * CDIM];

// ---------------- helpers ----------------------------------------------------
__device__ __forceinline__ uint32_t smem_u32(const void* p) {
    uint32_t a;
    asm("{ .reg .u64 t; cvta.to.shared.u64 t, %1; cvt.u32.u64 %0, t; }" : "=r"(a) : "l"(p));
    return a;
}
#define CP_ASYNC16(dst, src) \
    asm volatile("cp.async.cg.shared.global [%0], [%1], 16;" :: "r"(dst), "l"(src))
#define CP_COMMIT() asm volatile("cp.async.commit_group;" ::: "memory")
#define CP_WAIT(n)  asm volatile("cp.async.wait_group %0;" :: "n"(n) : "memory")

#define LDMATRIX_X4(r0, r1, r2, r3, addr) \
    asm volatile("ldmatrix.sync.aligned.m8n8.x4.shared.b16 {%0,%1,%2,%3}, [%4];" \
                 : "=r"(r0), "=r"(r1), "=r"(r2), "=r"(r3) : "r"(addr))
#define LDMATRIX_X4_T(r0, r1, r2, r3, addr) \
    asm volatile("ldmatrix.sync.aligned.m8n8.x4.trans.shared.b16 {%0,%1,%2,%3}, [%4];" \
                 : "=r"(r0), "=r"(r1), "=r"(r2), "=r"(r3) : "r"(addr))

#define MMA_16816(d, a, b0v, b1v) \
    asm volatile("mma.sync.aligned.m16n8k16.row.col.f32.bf16.bf16.f32 " \
                 "{%0,%1,%2,%3}, {%4,%5,%6,%7}, {%8,%9}, {%0,%1,%2,%3};" \
                 : "+f"((d)[0]), "+f"((d)[1]), "+f"((d)[2]), "+f"((d)[3]) \
                 : "r"((a)[0]), "r"((a)[1]), "r"((a)[2]), "r"((a)[3]), \
                   "r"(b0v), "r"(b1v))

__device__ __forceinline__ int map_win_to_global(int r) {
    int w = r >> 6, n = r & 63;
    int b = w >> 8, rem = w & 255;
    int wh = rem >> 4, ww = rem & 15;
    int i = n >> 3, j = n & 7;
    int h  = (wh * 8 + i + SS) & 127;
    int wc = (ww * 8 + j + SS) & 127;
    return (b << 14) + (h << 7) + wc;
}
__device__ __forceinline__ float gelu_exact(float v) {
    return 0.5f * v * (1.0f + erff(v * 0.70710678118654752440f));
}
__device__ __forceinline__ uint32_t pack_bf2(float a, float b) {
    __nv_bfloat162 h = __floats2bfloat162_rn(a, b);
    return *(uint32_t*)&h;
}

// ---------------- fp32 -> bf16 conversion -------------------------------------
__global__ void __launch_bounds__(256) conv_x_k(const float* __restrict__ src) {
    const size_t i = ((size_t)blockIdx.x * 256 + threadIdx.x) * 8;
    float4 v0 = *(const float4*)(src + i);
    float4 v1 = *(const float4*)(src + i + 4);
    uint4 o;
    o.x = pack_bf2(v0.x, v0.y); o.y = pack_bf2(v0.z, v0.w);
    o.z = pack_bf2(v1.x, v1.y); o.w = pack_bf2(v1.z, v1.w);
    *(uint4*)(g_xbf + i) = o;
}
#define S0 (CDIM*QKVN)
#define S1 (CDIM*CDIM)
#define S2 (CDIM*HID)
#define S3 (HID*CDIM)
__global__ void __launch_bounds__(256) conv_w_all(
    const float* __restrict__ w0, const float* __restrict__ w1,
    const float* __restrict__ w2, const float* __restrict__ w3)
{
    const int off = (blockIdx.x * 256 + threadIdx.x) * 8;
    const float* src; bf16* dst; int lo;
    if      (off < S0)            { src = w0; dst = g_wqkv;  lo = off; }
    else if (off < S0+S1)         { src = w1; dst = g_wproj; lo = off - S0; }
    else if (off < S0+S1+S2)      { src = w2; dst = g_w1;    lo = off - S0 - S1; }
    else if (off < S0+S1+S2+S3)   { src = w3; dst = g_w2;    lo = off - S0 - S1 - S2; }
    else return;
    float4 v0 = *(const float4*)(src + lo);
    float4 v1 = *(const float4*)(src + lo + 4);
    uint4 o;
    o.x = pack_bf2(v0.x, v0.y); o.y = pack_bf2(v0.z, v0.w);
    o.z = pack_bf2(v1.x, v1.y); o.w = pack_bf2(v1.z, v1.w);
    *(uint4*)(dst + lo) = o;
}

// ---------------- WMMA bf16 GEMM: 128x96, 4 warps, kk-preloaded fragments -----
// MODE: 0=QKV(gather A; out bf16 g_qkv)  1=PROJ(scatter+resid -> fp32 g_x1)
//       2=FC1(gelu -> bf16 g_h)          3=FC2(+resid g_x1 -> fp32 Cout)
template<int KDIM, int NDIM, int MODE>
__global__ void __launch_bounds__(128) gemm_bf(
    const float* __restrict__ bias,
    const float* __restrict__ resid,
    float* __restrict__ Cout)
{
    __shared__ __align__(16) unsigned char smem[SMEM_BYTES];
    bf16* sA[2] = { (bf16*)smem, (bf16*)(smem + STAGE_B) };
    bf16* sB[2] = { (bf16*)(smem + A_STAGE_B), (bf16*)(smem + STAGE_B + A_STAGE_B) };
    float* sC = (float*)smem;

    const int tid = threadIdx.x;
    const int bm = blockIdx.y * BM;
    const int bn = blockIdx.x * BN;

    const bf16* Aptr;
    const bf16* Bptr;
    if      constexpr (MODE == 0) { Aptr = g_xbf;     Bptr = g_wqkv; }
    else if constexpr (MODE == 1) { Aptr = g_attnout; Bptr = g_wproj; }
    else if constexpr (MODE == 2) { Aptr = g_x1n;     Bptr = g_w1; }
    else                          { Aptr = g_h;       Bptr = g_w2; }

    int grA;
    if constexpr (MODE == 0) grA = map_win_to_global(bm + tid);
    else                     grA = bm + tid;
    const bf16* srcA = Aptr + (size_t)grA * KDIM;
    const uint32_t dA0 = smem_u32(sA[0]) + (uint32_t)(tid * LDA * 2);
    const uint32_t dA1 = smem_u32(sA[1]) + (uint32_t)(tid * LDA * 2);

    int bRow[3], bCol[3];
    const bf16* srcB[3];
    uint32_t dBoff[3];
    #pragma unroll
    for (int l = 0; l < 3; l++) {
        int idx = tid + l * 128;
        bRow[l] = idx / 12; bCol[l] = (idx % 12) * 8;
        srcB[l] = Bptr + (size_t)bRow[l] * NDIM + bn + bCol[l];
        dBoff[l] = (uint32_t)((bRow[l] * LDB + bCol[l]) * 2);
    }
    const uint32_t dBb[2] = { smem_u32(sB[0]), smem_u32(sB[1]) };

    constexpr int T = KDIM / BK;
    const int wid = tid >> 5;
    const int wm = wid & 1, wn = wid >> 1;

    wmma::fragment<wmma::accumulator, 16, 16, 16, float> cf[4][3];
    #pragma unroll
    for (int i = 0; i < 4; i++)
        #pragma unroll
        for (int j = 0; j < 3; j++) wmma::fill_fragment(cf[i][j], 0.0f);

    #pragma unroll
    for (int c = 0; c < 4; c++) CP_ASYNC16(dA0 + c * 16, srcA + c * 8);
    #pragma unroll
    for (int l = 0; l < 3; l++) CP_ASYNC16(dBb[0] + dBoff[l], srcB[l]);
    CP_COMMIT();

    for (int t = 0; t < T; t++) {
        if (t + 1 < T) {
            const int k0 = (t + 1) * BK;
            const uint32_t dAx = ((t + 1) & 1) ? dA1 : dA0;
            const uint32_t dBx = dBb[(t + 1) & 1];
            #pragma unroll
            for (int c = 0; c < 4; c++) CP_ASYNC16(dAx + c * 16, srcA + k0 + c * 8);
            #pragma unroll
            for (int l = 0; l < 3; l++) CP_ASYNC16(dBx + dBoff[l], srcB[l] + (size_t)k0 * NDIM);
            CP_COMMIT();
            CP_WAIT(1);
        } else {
            CP_WAIT(0);
        }
        __syncthreads();

        const bf16* At = sA[t & 1];
        const bf16* Bt = sB[t & 1];

        // preload BOTH kk-halves' fragments, then issue all mma back-to-back
        wmma::fragment<wmma::matrix_a, 16, 16, 16, bf16, wmma::row_major> af[2][4];
        wmma::fragment<wmma::matrix_b, 16, 16, 16, bf16, wmma::row_major> bf_[2][3];
        #pragma unroll
        for (int s = 0; s < 2; s++) {
            #pragma unroll
            for (int i = 0; i < 4; i++)
                wmma::load_matrix_sync(af[s][i], At + (wm * 64 + i * 16) * LDA + s * 16, LDA);
            #pragma unroll
            for (int j = 0; j < 3; j++)
                wmma::load_matrix_sync(bf_[s][j], Bt + s * 16 * LDB + wn * 48 + j * 16, LDB);
        }
        #pragma unroll
        for (int s = 0; s < 2; s++)
            #pragma unroll
            for (int i = 0; i < 4; i++)
                #pragma unroll
                for (int j = 0; j < 3; j++)
                    wmma::mma_sync(cf[i][j], af[s][i], bf_[s][j], cf[i][j]);
        __syncthreads();
    }

    #pragma unroll
    for (int h = 0; h < 2; h++) {
        if (wm == h) {
            #pragma unroll
            for (int i = 0; i < 4; i++)
                #pragma unroll
                for (int j = 0; j < 3; j++)
                    wmma::store_matrix_sync(sC + (i * 16) * LDC + wn * 48 + j * 16,
                                            cf[i][j], LDC, wmma::mem_row_major);
        }
        __syncthreads();

        const int row  = tid >> 1;
        const int half = tid & 1;
        const int c0   = half * 48;
        const int m    = bm + h * 64 + row;
        float v[48];
        #pragma unroll
        for (int c4 = 0; c4 < 12; c4++) {
            float4 w4 = *(const float4*)(sC + row * LDC + c0 + c4 * 4);
            const int gc = bn + c0 + c4 * 4;
            v[c4*4+0] = w4.x + __ldg(bias + gc + 0);
            v[c4*4+1] = w4.y + __ldg(bias + gc + 1);
            v[c4*4+2] = w4.z + __ldg(bias + gc + 2);
            v[c4*4+3] = w4.w + __ldg(bias + gc + 3);
        }

        if constexpr (MODE == 0) {
            bf16* dst = g_qkv + (size_t)m * QKVN + bn + c0;
            #pragma unroll
            for (int g = 0; g < 6; g++) {
                uint4 o;
                o.x = pack_bf2(v[g*8+0], v[g*8+1]); o.y = pack_bf2(v[g*8+2], v[g*8+3]);
                o.z = pack_bf2(v[g*8+4], v[g*8+5]); o.w = pack_bf2(v[g*8+6], v[g*8+7]);
                *(uint4*)(dst + g * 8) = o;
            }
        } else if constexpr (MODE == 1) {
            const int grow = map_win_to_global(m);
            const size_t o = (size_t)grow * CDIM + bn + c0;
            #pragma unroll
            for (int c4 = 0; c4 < 12; c4++) {
                float4 r = *(const float4*)(resid + o + c4 * 4);
                *(float4*)(g_x1 + o + c4 * 4) =
                    make_float4(v[c4*4+0] + r.x, v[c4*4+1] + r.y, v[c4*4+2] + r.z, v[c4*4+3] + r.w);
            }
        } else if constexpr (MODE == 2) {
            bf16* dst = g_h + (size_t)m * HID + bn + c0;
            #pragma unroll
            for (int g = 0; g < 6; g++) {
                uint4 o;
                o.x = pack_bf2(gelu_exact(v[g*8+0]), gelu_exact(v[g*8+1]));
                o.y = pack_bf2(gelu_exact(v[g*8+2]), gelu_exact(v[g*8+3]));
                o.z = pack_bf2(gelu_exact(v[g*8+4]), gelu_exact(v[g*8+5]));
                o.w = pack_bf2(gelu_exact(v[g*8+6]), gelu_exact(v[g*8+7]));
                *(uint4*)(dst + g * 8) = o;
            }
        } else {
            const size_t o = (size_t)m * CDIM + bn + c0;
            #pragma unroll
            for (int c4 = 0; c4 < 12; c4++) {
                float4 r = *(const float4*)(g_x1 + o + c4 * 4);
                *(float4*)(Cout + o + c4 * 4) =
                    make_float4(v[c4*4+0] + r.x, v[c4*4+1] + r.y, v[c4*4+2] + r.z, v[c4*4+3] + r.w);
            }
        }
        __syncthreads();
    }
}

// ---------------- LayerNorm: one warp per token, bf16 out ---------------------
__global__ void __launch_bounds__(256) ln_norm_k(const float* __restrict__ gamma,
                                                 const float* __restrict__ beta)
{
    const int r = blockIdx.x * 8 + (threadIdx.x >> 5);
    const int lane = threadIdx.x & 31;
    const float* p = g_x1 + (size_t)r * CDIM;
    float v[6];
    float s = 0.f, ss = 0.f;
    #pragma unroll
    for (int k = 0; k < 6; k++) {
        v[k] = p[lane + k * 32];
        s += v[k]; ss += v[k] * v[k];
    }
    #pragma unroll
    for (int o = 16; o; o >>= 1) {
        s  += __shfl_xor_sync(0xffffffffu, s,  o);
        ss += __shfl_xor_sync(0xffffffffu, ss, o);
    }
    const float mu = s * (1.f / 192.f);
    const float var = ss * (1.f / 192.f) - mu * mu;
    const float rs = rsqrtf(var + 1e-5f);
    bf16* q = g_x1n + (size_t)r * CDIM;
    #pragma unroll
    for (int k = 0; k < 6; k++) {
        const int c = lane + k * 32;
        q[c] = __float2bfloat16_rn((v[k] - mu) * rs * __ldg(gamma + c) + __ldg(beta + c));
    }
}

// ---------------- attention: register-resident S, trans-ldmatrix V (R14) ------
#define ALQ 40     // sQ/sK/sV row stride (bf16)

__global__ void __launch_bounds__(128) attn_tc(const float* __restrict__ rpb)
{
    const int w = blockIdx.x, head = blockIdx.y;
    const int tid = threadIdx.x;
    const int wid = tid >> 5, lane = tid & 31;

    __shared__ __align__(16) bf16 sQ[64 * ALQ];
    __shared__ __align__(16) bf16 sK[64 * ALQ];
    __shared__ __align__(16) bf16 sV[64 * ALQ];
    __shared__ float sRp[225];
    __shared__ int   sReg[64];

    const bf16* base = g_qkv + (size_t)w * 64 * QKVN + head * 32;
    #pragma unroll
    for (int l = 0; l < 2; l++) {
        int i = tid + l * 128;
        int row = i >> 2, cg = (i & 3) * 8;
        const bf16* src = base + (size_t)row * QKVN;
        *(uint4*)(sQ + row * ALQ + cg) = *(const uint4*)(src + cg);
        *(uint4*)(sK + row * ALQ + cg) = *(const uint4*)(src + CDIM + cg);
        *(uint4*)(sV + row * ALQ + cg) = *(const uint4*)(src + 2 * CDIM + cg);
    }
    for (int i = tid; i < 225; i += 128) sRp[i] = rpb[i * NHEAD + head];
    if (tid < 64) {
        int rem = w & 255; int wh = rem >> 4, ww = rem & 15;
        int hs  = wh * 8 + (tid >> 3);
        int wsc = ww * 8 + (tid & 7);
        int rh = hs  < 120 ? 0 : (hs  < 124 ? 1 : 2);
        int rw = wsc < 120 ? 0 : (wsc < 124 ? 1 : 2);
        sReg[tid] = rh * 3 + rw;
    }
    __syncthreads();

    const int r0 = wid * 16;
    const int qr = lane >> 2;
    const int qc = lane & 3;
    const uint32_t sQa = smem_u32(sQ), sKa = smem_u32(sK), sVa = smem_u32(sV);

    uint32_t aq[2][4];
    #pragma unroll
    for (int kk = 0; kk < 2; kk++) {
        uint32_t addr = sQa + (uint32_t)((r0 + (lane & 15)) * ALQ * 2 + kk * 32 + (lane >> 4) * 16);
        LDMATRIX_X4(aq[kk][0], aq[kk][1], aq[kk][2], aq[kk][3], addr);
    }

    float acc[8][4];
    #pragma unroll
    for (int nb = 0; nb < 8; nb++) {
        acc[nb][0] = acc[nb][1] = acc[nb][2] = acc[nb][3] = 0.f;
        uint32_t kb0, kb1, kb2, kb3;
        uint32_t addr = sKa + (uint32_t)((8 * nb + (lane & 7)) * ALQ * 2 + (lane >> 3) * 16);
        LDMATRIX_X4(kb0, kb1, kb2, kb3, addr);
        MMA_16816(acc[nb], aq[0], kb0, kb1);
        MMA_16816(acc[nb], aq[1], kb2, kb3);
    }

    const int grow0 = r0 + qr, grow1 = grow0 + 8;
    const int i10 = grow0 >> 3, j10 = grow0 & 7, reg0 = sReg[grow0];
    const int i11 = grow1 >> 3, j11 = grow1 & 7, reg1 = sReg[grow1];
    const float scale = 0.17677669529663689f;
    float sum0 = 0.f, sum1 = 0.f;
    #pragma unroll
    for (int nb = 0; nb < 8; nb++) {
        #pragma unroll
        for (int e = 0; e < 2; e++) {
            const int c = 8 * nb + 2 * qc + e;
            const int j2 = c & 7;
            const int rc = sReg[c];
            const float m0 = (rc == reg0) ? 0.f : -100.f;
            const float m1 = (rc == reg1) ? 0.f : -100.f;
            const float b0 = sRp[(i10 - nb + 7) * 15 + (j10 - j2 + 7)];
            const float b1 = sRp[(i11 - nb + 7) * 15 + (j11 - j2 + 7)];
            float e0 = __expf(acc[nb][e]     * scale + b0 + m0);
            float e1 = __expf(acc[nb][2 + e] * scale + b1 + m1);
            acc[nb][e] = e0;     sum0 += e0;
            acc[nb][2 + e] = e1; sum1 += e1;
        }
    }
    sum0 += __shfl_xor_sync(0xffffffffu, sum0, 1);
    sum0 += __shfl_xor_sync(0xffffffffu, sum0, 2);
    sum1 += __shfl_xor_sync(0xffffffffu, sum1, 1);
    sum1 += __shfl_xor_sync(0xffffffffu, sum1, 2);
    const float inv0 = 1.f / sum0, inv1 = 1.f / sum1;

    uint32_t pa[4][4];
    #pragma unroll
    for (int kk = 0; kk < 4; kk++) {
        const int na = 2 * kk, nbb = 2 * kk + 1;
        pa[kk][0] = pack_bf2(acc[na][0] * inv0, acc[na][1] * inv0);
        pa[kk][1] = pack_bf2(acc[na][2] * inv1, acc[na][3] * inv1);
        pa[kk][2] = pack_bf2(acc[nbb][0] * inv0, acc[nbb][1] * inv0);
        pa[kk][3] = pack_bf2(acc[nbb][2] * inv1, acc[nbb][3] * inv1);
    }

    float oacc[4][4];
    #pragma unroll
    for (int nd = 0; nd < 4; nd++) {
        oacc[nd][0] = oacc[nd][1] = oacc[nd][2] = oacc[nd][3] = 0.f;
        uint32_t vb0, vb1, vb2, vb3;
        uint32_t addr = sVa + (uint32_t)(lane * ALQ * 2 + nd * 16);
        LDMATRIX_X4_T(vb0, vb1, vb2, vb3, addr);                 // keys 0..31
        MMA_16816(oacc[nd], pa[0], vb0, vb1);
        MMA_16816(oacc[nd], pa[1], vb2, vb3);
        addr = sVa + (uint32_t)((32 + lane) * ALQ * 2 + nd * 16);
        LDMATRIX_X4_T(vb0, vb1, vb2, vb3, addr);                 // keys 32..63
        MMA_16816(oacc[nd], pa[2], vb0, vb1);
        MMA_16816(oacc[nd], pa[3], vb2, vb3);
    }

    bf16* op0 = g_attnout + ((size_t)(w * 64 + grow0)) * CDIM + head * 32 + 2 * qc;
    bf16* op1 = g_attnout + ((size_t)(w * 64 + grow1)) * CDIM + head * 32 + 2 * qc;
    #pragma unroll
    for (int nd = 0; nd < 4; nd++) {
        *(uint32_t*)(op0 + 8 * nd) = pack_bf2(oacc[nd][0], oacc[nd][1]);
        *(uint32_t*)(op1 + 8 * nd) = pack_bf2(oacc[nd][2], oacc[nd][3]);
    }
}

// ---------------- launch -----------------------------------------------------
extern "C" void kernel_launch(void* const* d_in, const int* in_sizes, int n_in,
                              void* d_out, int out_size)
{
    const float* x       = (const float*)d_in[0];
    const float* qkv_w   = (const float*)d_in[1];
    const float* qkv_b   = (const float*)d_in[2];
    const float* proj_w  = (const float*)d_in[3];
    const float* proj_b  = (const float*)d_in[4];
    const float* rpb     = (const float*)d_in[5];
    const float* norm2_g = (const float*)d_in[6];
    const float* norm2_b = (const float*)d_in[7];
    const float* mlp_w1  = (const float*)d_in[8];
    const float* mlp_b1  = (const float*)d_in[9];
    const float* mlp_w2  = (const float*)d_in[10];
    const float* mlp_b2  = (const float*)d_in[11];
    float* out = (float*)d_out;

    // precision conversions
    conv_x_k<<<TOK * CDIM / (256 * 8), 256>>>(x);
    conv_w_all<<<(S0 + S1 + S2 + S3) / (256 * 8), 256>>>(qkv_w, proj_w, mlp_w1, mlp_w2);

    // 1) QKV = gather(x) @ qkv_w + b  -> bf16 g_qkv (window order)
    gemm_bf<192, 576, 0><<<dim3(6, 1024), 128>>>(qkv_b, nullptr, nullptr);
    // 2) windowed attention (register-resident softmax) -> bf16 g_attnout
    attn_tc<<<dim3(NWIN, NHEAD), 128>>>(rpb);
    // 3) proj + scatter + residual -> fp32 g_x1
    gemm_bf<192, 192, 1><<<dim3(2, 1024), 128>>>(proj_b, x, nullptr);
    // 4) LayerNorm(g_x1) -> bf16 g_x1n
    ln_norm_k<<<TOK / 8, 256>>>(norm2_g, norm2_b);
    // 5) fc1 + GELU -> bf16 g_h
    gemm_bf<192, 768, 2><<<dim3(8, 1024), 128>>>(mlp_b1, nullptr, nullptr);
    // 6) fc2 + residual -> fp32 out
    gemm_bf<768, 192, 3><<<dim3(2, 1024), 128>>>(mlp_b2, nullptr, out);
}